// round 11
// baseline (speedup 1.0000x reference)
#include <cuda_runtime.h>
#include <math.h>

#define Bq 256
#define Tq 512
#define Iq 12
#define Hq 1024
#define Zq 128
#define G3 3072
#define NBLK 128
#define NTHR 512
#define NWARP 2048
#define OFF_MEAN (Bq*Tq*Iq)
#define OFF_STD  (OFF_MEAN + Bq*Zq)

__device__ float g_hf[2][Bq*Hq];
__device__ float g_hb[2][Bq*Hq];
__device__ float g_hd[2][Bq*Hq];
__device__ float g_z[Bq*Zq];
__device__ float g_giz[Bq*G3];
__device__ unsigned g_cnt = 0;
__device__ unsigned g_gen = 0;

struct Smem {
    float As[32][132];        // [k][m]
    float2 Wd[3][32][34];     // [gate][k][n] duplicated (w,w)
    float Xs[128][Iq];
    float2 Wid[3][32][Iq];    // epilogue weights duplicated
};

__device__ __forceinline__ unsigned long long pk2(float lo, float hi){
    unsigned long long r; asm("mov.b64 %0, {%1,%2};" : "=l"(r) : "f"(lo), "f"(hi)); return r;
}
__device__ __forceinline__ void up2(unsigned long long v, float& lo, float& hi){
    asm("mov.b64 {%0,%1}, %2;" : "=f"(lo), "=f"(hi) : "l"(v));
}
__device__ __forceinline__ void fma2(unsigned long long& a, unsigned long long x, unsigned long long y){
    asm("fma.rn.f32x2 %0, %1, %2, %0;" : "+l"(a) : "l"(x), "l"(y));
}
__device__ __forceinline__ unsigned long long lds2(const float* p){
    return *reinterpret_cast<const unsigned long long*>(p);
}
__device__ __forceinline__ float sgm(float v){ return 1.f/(1.f + expf(-v)); }
__device__ __forceinline__ float wred(float v){
    #pragma unroll
    for (int o = 16; o > 0; o >>= 1) v += __shfl_down_sync(0xffffffffu, v, o);
    return v;
}

__device__ __forceinline__ void gbar(){
    __syncthreads();
    if (threadIdx.x == 0){
        unsigned my = *(volatile unsigned*)&g_gen;
        __threadfence();
        if (atomicAdd(&g_cnt, 1u) == NBLK - 1u){
            atomicExch(&g_cnt, 0u);
            __threadfence();
            atomicAdd(&g_gen, 1u);
        } else {
            while (*(volatile unsigned*)&g_gen == my) __nanosleep(32);
            __threadfence();
        }
    }
    __syncthreads();
}

template<int DEC>
__device__ __forceinline__ void emit(float sr, float sz, float sn, float gx,
    int m, int j, float br, float bz, float bn, float cr, float cz, float cn,
    const float* __restrict__ hold, float* __restrict__ hnew)
{
    float gr = br, gz = bz, gn = bn;
    if (DEC){
        gr = __ldcg(&g_giz[m*G3 + j]);
        gz = __ldcg(&g_giz[m*G3 + Hq + j]);
        gn = __ldcg(&g_giz[m*G3 + 2*Hq + j]);
    }
    float rr = sgm(sr + gr + cr);
    float zz = sgm(sz + gz + cz);
    float nn = tanhf(gx + gn + rr*(sn + cn));
    float ho = __ldcg(&hold[m*Hq + j]);
    hnew[m*Hq + j] = (1.f - zz)*nn + zz*ho;
}

// MR rows/thread (8 -> BM=128 encoder, 4 -> BM=64 decoder); f32x2 packs M-row pairs.
template<int MR, int DEC>
__device__ __forceinline__ void gru_tile(Smem* sm,
    const float* __restrict__ x, int tt,
    const float* __restrict__ Wih, int ihs,
    const float* __restrict__ Whh,
    const float* __restrict__ bih, const float* __restrict__ bhh,
    const float* __restrict__ hold, float* __restrict__ hnew,
    int m0, int n0)
{
    const int BM = MR*16, NR = BM/16, NP = MR/2;
    const int tid = threadIdx.x;
    const int tx = tid & 31, ty = tid >> 5;
    const int mr0 = ty*MR;
    const int j = n0 + tx;
    const int lane = tx, ar0 = ty*NR;
    const int wrow = tid >> 2;              // tid < 384
    const int wg = wrow >> 5, wn = wrow & 31, wk = (tid & 3)*8;

    __syncthreads();
    for (int idx = tid; idx < BM*Iq; idx += NTHR){
        int r = idx/Iq, c = idx - r*Iq;
        float v;
        if (DEC && tt == 0) v = (c == Iq-1) ? 1.f : 0.f;
        else v = __ldg(&x[(m0 + r)*(Tq*Iq) + (DEC ? tt-1 : tt)*Iq + c]);
        sm->Xs[r][c] = v;
    }
    for (int idx = tid; idx < 3*32*Iq; idx += NTHR){
        int g = idx/(32*Iq); int rem = idx - g*32*Iq; int n = rem/Iq, c = rem - n*Iq;
        float v = __ldg(&Wih[(g*Hq + n0 + n)*ihs + c]);
        sm->Wid[g][n][c] = make_float2(v, v);
    }

    unsigned long long accr[NP], accz[NP], accn[NP], ginx[NP];
    #pragma unroll
    for (int i = 0; i < NP; i++){ accr[i]=0ull; accz[i]=0ull; accn[i]=0ull; ginx[i]=0ull; }

    float pa[8]; float4 pw0, pw1;
    const float* ab = hold + (m0 + ar0)*Hq + lane;
    const float* wb = (tid < 384) ? (Whh + (wg*Hq + n0 + wn)*Hq + wk) : Whh;
    #pragma unroll
    for (int r = 0; r < NR; r++) pa[r] = __ldcg(ab + r*Hq);
    pw0 = __ldg((const float4*)wb); pw1 = __ldg((const float4*)(wb + 4));

    for (int kb = 0; kb < 32; kb++){
        __syncthreads();
        #pragma unroll
        for (int q = 0; q < NR/4; q++)
            *(float4*)&sm->As[lane][ar0 + 4*q] =
                make_float4(pa[4*q], pa[4*q+1], pa[4*q+2], pa[4*q+3]);
        if (tid < 384){
            sm->Wd[wg][wk+0][wn] = make_float2(pw0.x, pw0.x);
            sm->Wd[wg][wk+1][wn] = make_float2(pw0.y, pw0.y);
            sm->Wd[wg][wk+2][wn] = make_float2(pw0.z, pw0.z);
            sm->Wd[wg][wk+3][wn] = make_float2(pw0.w, pw0.w);
            sm->Wd[wg][wk+4][wn] = make_float2(pw1.x, pw1.x);
            sm->Wd[wg][wk+5][wn] = make_float2(pw1.y, pw1.y);
            sm->Wd[wg][wk+6][wn] = make_float2(pw1.z, pw1.z);
            sm->Wd[wg][wk+7][wn] = make_float2(pw1.w, pw1.w);
        }
        __syncthreads();
        if (kb < 31){
            int ko = (kb+1)*32;
            #pragma unroll
            for (int r = 0; r < NR; r++) pa[r] = __ldcg(ab + ko + r*Hq);
            pw0 = __ldg((const float4*)(wb + ko)); pw1 = __ldg((const float4*)(wb + ko + 4));
        }
        #pragma unroll 8
        for (int k = 0; k < 32; k++){
            unsigned long long wr  = lds2(&sm->Wd[0][k][tx].x);
            unsigned long long wz  = lds2(&sm->Wd[1][k][tx].x);
            unsigned long long wn2 = lds2(&sm->Wd[2][k][tx].x);
            ulonglong2 a0 = *(const ulonglong2*)&sm->As[k][mr0];
            fma2(accr[0],a0.x,wr); fma2(accz[0],a0.x,wz); fma2(accn[0],a0.x,wn2);
            fma2(accr[1],a0.y,wr); fma2(accz[1],a0.y,wz); fma2(accn[1],a0.y,wn2);
            if (MR == 8){
                ulonglong2 a1 = *(const ulonglong2*)&sm->As[k][mr0 + 4];
                fma2(accr[2],a1.x,wr); fma2(accz[2],a1.x,wz); fma2(accn[2],a1.x,wn2);
                fma2(accr[3],a1.y,wr); fma2(accz[3],a1.y,wz); fma2(accn[3],a1.y,wn2);
            }
        }
    }

    #pragma unroll
    for (int c = 0; c < Iq; c++){
        unsigned long long wr  = lds2(&sm->Wid[0][tx][c].x);
        unsigned long long wz  = lds2(&sm->Wid[1][tx][c].x);
        unsigned long long wn2 = lds2(&sm->Wid[2][tx][c].x);
        #pragma unroll
        for (int p = 0; p < NP; p++){
            unsigned long long b = pk2(sm->Xs[mr0+2*p][c], sm->Xs[mr0+2*p+1][c]);
            fma2(accr[p],b,wr); fma2(accz[p],b,wz); fma2(ginx[p],b,wn2);
        }
    }

    float cr = __ldg(&bhh[j]), cz = __ldg(&bhh[Hq+j]), cn = __ldg(&bhh[2*Hq+j]);
    float br = 0, bz = 0, bn = 0;
    if (!DEC){ br = __ldg(&bih[j]); bz = __ldg(&bih[Hq+j]); bn = __ldg(&bih[2*Hq+j]); }

    #pragma unroll
    for (int p = 0; p < NP; p++){
        float sr0,sr1,sz0,sz1,sn0,sn1,gx0,gx1;
        up2(accr[p],sr0,sr1); up2(accz[p],sz0,sz1); up2(accn[p],sn0,sn1); up2(ginx[p],gx0,gx1);
        int m = m0 + mr0 + 2*p;
        emit<DEC>(sr0,sz0,sn0,gx0, m,   j, br,bz,bn, cr,cz,cn, hold, hnew);
        emit<DEC>(sr1,sz1,sn1,gx1, m+1, j, br,bz,bn, cr,cz,cn, hold, hnew);
    }
}

__global__ void __launch_bounds__(NTHR, 1) vae_kernel(
    const float* __restrict__ x, const float* __restrict__ noise,
    const float* __restrict__ Wih_f, const float* __restrict__ Whh_f,
    const float* __restrict__ bih_f, const float* __restrict__ bhh_f,
    const float* __restrict__ Wih_b, const float* __restrict__ Whh_b,
    const float* __restrict__ bih_b, const float* __restrict__ bhh_b,
    const float* __restrict__ Wmu,  const float* __restrict__ bmu,
    const float* __restrict__ Wvar, const float* __restrict__ bvar,
    const float* __restrict__ Winit,const float* __restrict__ binit,
    const float* __restrict__ Wout, const float* __restrict__ bout,
    const float* __restrict__ Wcih, const float* __restrict__ Wchh,
    const float* __restrict__ bcih, const float* __restrict__ bchh,
    float* __restrict__ out)
{
    __shared__ Smem sm;
    const int blk = blockIdx.x, tid = threadIdx.x;
    const int lane = tid & 31;
    const int gwp = blk*16 + (tid >> 5);

    for (int i = blk*NTHR + tid; i < Bq*Hq; i += NBLK*NTHR){
        g_hf[0][i] = 0.f; g_hb[0][i] = 0.f;
    }
    gbar();

    const int edir = blk >> 6, erem = blk & 63;
    const int em0 = (erem >> 5)*128, en0 = (erem & 31)*32;
    for (int t = 0; t < Tq; t++){
        int par = t & 1;
        if (edir == 0)
            gru_tile<8,0>(&sm, x, t, Wih_f, Iq, Whh_f, bih_f, bhh_f,
                          g_hf[par], g_hf[par^1], em0, en0);
        else
            gru_tile<8,0>(&sm, x, Tq-1-t, Wih_b, Iq, Whh_b, bih_b, bhh_b,
                          g_hb[par], g_hb[par^1], em0, en0);
        gbar();
    }

    for (int it = gwp; it < Bq*Zq; it += NWARP){
        int m = it >> 7, zi = it & 127;
        const float* hf = &g_hf[0][m*Hq];
        const float* hb = &g_hb[0][m*Hq];
        const float* wm = &Wmu[zi*2*Hq];
        const float* wv = &Wvar[zi*2*Hq];
        float am = 0.f, av = 0.f;
        for (int k = lane; k < Hq; k += 32){
            float h1 = __ldcg(&hf[k]); am += h1*__ldg(&wm[k]);    av += h1*__ldg(&wv[k]);
            float h2 = __ldcg(&hb[k]); am += h2*__ldg(&wm[Hq+k]); av += h2*__ldg(&wv[Hq+k]);
        }
        am = wred(am); av = wred(av);
        if (lane == 0){
            float mean = am + __ldg(&bmu[zi]);
            float sd = expf(0.5f*(av + __ldg(&bvar[zi])));
            out[OFF_MEAN + m*Zq + zi] = mean;
            out[OFF_STD  + m*Zq + zi] = sd;
            g_z[m*Zq + zi] = mean + sd*__ldg(&noise[m*Zq + zi]);
        }
    }
    gbar();

    for (int it = gwp; it < Bq*G3; it += NWARP){
        int m = it / G3, gc = it - m*G3;
        const float* zr = &g_z[m*Zq];
        const float* wr = &Wcih[gc*(Iq + Zq) + Iq];
        float acc = 0.f;
        for (int k = lane; k < Zq; k += 32) acc += __ldcg(&zr[k])*__ldg(&wr[k]);
        acc = wred(acc);
        if (lane == 0) g_giz[m*G3 + gc] = acc + __ldg(&bcih[gc]);
    }
    for (int it = gwp; it < Bq*Hq; it += NWARP){
        int m = it >> 10, jj = it & 1023;
        const float* zr = &g_z[m*Zq];
        const float* wr = &Winit[jj*Zq];
        float acc = 0.f;
        for (int k = lane; k < Zq; k += 32) acc += __ldcg(&zr[k])*__ldg(&wr[k]);
        acc = wred(acc);
        if (lane == 0) g_hd[0][m*Hq + jj] = tanhf(acc + __ldg(&binit[jj]));
    }
    gbar();

    const int dm0 = (blk >> 5)*64, dn0 = (blk & 31)*32;
    for (int t = 0; t < Tq; t++){
        int par = t & 1;
        if (t > 0){
            const float* hbuf = g_hd[par];
            for (int it = gwp; it < Bq*Iq; it += NWARP){
                int m = it / Iq, i = it - m*Iq;
                const float* h = &hbuf[m*Hq];
                const float* w = &Wout[i*Hq];
                float acc = 0.f;
                for (int k = lane; k < Hq; k += 32) acc += __ldcg(&h[k])*__ldg(&w[k]);
                acc = wred(acc);
                if (lane == 0)
                    out[m*(Tq*Iq) + (t-1)*Iq + i] = sgm(acc + __ldg(&bout[i]));
            }
        }
        gru_tile<4,1>(&sm, x, t, Wcih, Iq + Zq, Wchh, bcih, bchh,
                      g_hd[par], g_hd[par^1], dm0, dn0);
        gbar();
    }

    {
        const float* hbuf = g_hd[0];
        for (int it = gwp; it < Bq*Iq; it += NWARP){
            int m = it / Iq, i = it - m*Iq;
            const float* h = &hbuf[m*Hq];
            const float* w = &Wout[i*Hq];
            float acc = 0.f;
            for (int k = lane; k < Hq; k += 32) acc += __ldcg(&h[k])*__ldg(&w[k]);
            acc = wred(acc);
            if (lane == 0)
                out[m*(Tq*Iq) + (Tq-1)*Iq + i] = sgm(acc + __ldg(&bout[i]));
        }
    }
}

extern "C" void kernel_launch(void* const* d_in, const int* in_sizes, int n_in,
                              void* d_out, int out_size)
{
    vae_kernel<<<NBLK, NTHR>>>(
        (const float*)d_in[0],  (const float*)d_in[1],
        (const float*)d_in[2],  (const float*)d_in[3],
        (const float*)d_in[4],  (const float*)d_in[5],
        (const float*)d_in[6],  (const float*)d_in[7],
        (const float*)d_in[8],  (const float*)d_in[9],
        (const float*)d_in[10], (const float*)d_in[11],
        (const float*)d_in[12], (const float*)d_in[13],
        (const float*)d_in[14], (const float*)d_in[15],
        (const float*)d_in[16], (const float*)d_in[17],
        (const float*)d_in[18], (const float*)d_in[19],
        (const float*)d_in[20], (const float*)d_in[21],
        (float*)d_out);
}

// round 12
// speedup vs baseline: 1.3134x; 1.3134x over previous
#include <cuda_runtime.h>
#include <math.h>

#define Bq 256
#define Tq 512
#define Iq 12
#define Hq 1024
#define Zq 128
#define G3 3072
#define NBLK 128
#define NTHR 512
#define NWARP 2048
#define OFF_MEAN (Bq*Tq*Iq)
#define OFF_STD  (OFF_MEAN + Bq*Zq)

__device__ float g_hf[2][Bq*Hq];
__device__ float g_hb[2][Bq*Hq];
__device__ float g_hd[2][Bq*Hq];
__device__ float g_z[Bq*Zq];
__device__ float g_giz[Bq*G3];
__device__ unsigned g_cnt = 0;
__device__ unsigned g_gen = 0;

struct Smem {
    float2 As2[16][130];      // [k-pair][m] (+2 pad) — broadcast LDS.128 reads
    float2 Ws2[3][32][17];    // [gate][n][k-pair] (+1 pad) — conflict-free LDS.64
    float Xs[128][Iq];
    float Wis[3][32][Iq];
};

__device__ __forceinline__ void up2(unsigned long long v, float& lo, float& hi){
    asm("mov.b64 {%0,%1}, %2;" : "=f"(lo), "=f"(hi) : "l"(v));
}
__device__ __forceinline__ void fma2(unsigned long long& a, unsigned long long x, unsigned long long y){
    asm("fma.rn.f32x2 %0, %1, %2, %0;" : "+l"(a) : "l"(x), "l"(y));
}
__device__ __forceinline__ unsigned long long lds2(const float* p){
    return *reinterpret_cast<const unsigned long long*>(p);
}
__device__ __forceinline__ float sgm(float v){ return 1.f/(1.f + expf(-v)); }
__device__ __forceinline__ float wred(float v){
    #pragma unroll
    for (int o = 16; o > 0; o >>= 1) v += __shfl_down_sync(0xffffffffu, v, o);
    return v;
}

__device__ __forceinline__ void gbar(){
    __syncthreads();
    if (threadIdx.x == 0){
        unsigned my = *(volatile unsigned*)&g_gen;
        __threadfence();
        if (atomicAdd(&g_cnt, 1u) == NBLK - 1u){
            atomicExch(&g_cnt, 0u);
            __threadfence();
            atomicAdd(&g_gen, 1u);
        } else {
            while (*(volatile unsigned*)&g_gen == my) __nanosleep(32);
            __threadfence();
        }
    }
    __syncthreads();
}

template<int DEC>
__device__ __forceinline__ void emit(float sr, float sz, float sn, float gx,
    int m, int j, float br, float bz, float bn, float cr, float cz, float cn,
    const float* __restrict__ hold, float* __restrict__ hnew)
{
    float gr = br, gz = bz, gn = bn;
    if (DEC){
        gr = __ldcg(&g_giz[m*G3 + j]);
        gz = __ldcg(&g_giz[m*G3 + Hq + j]);
        gn = __ldcg(&g_giz[m*G3 + 2*Hq + j]);
    }
    float rr = sgm(sr + gr + cr);
    float zz = sgm(sz + gz + cz);
    float nn = tanhf(gx + gn + rr*(sn + cn));
    float ho = __ldcg(&hold[m*Hq + j]);
    hnew[m*Hq + j] = (1.f - zz)*nn + zz*ho;
}

// MR rows/thread: 8 -> BM=128 (encoder), 4 -> BM=64 (decoder).
// f32x2 packs consecutive-K pairs; accumulators hold even/odd-k partials.
template<int MR, int DEC>
__device__ __forceinline__ void gru_tile(Smem* sm,
    const float* __restrict__ x, int tt,
    const float* __restrict__ Wih, int ihs,
    const float* __restrict__ Whh,
    const float* __restrict__ bih, const float* __restrict__ bhh,
    const float* __restrict__ hold, float* __restrict__ hnew,
    int m0, int n0)
{
    const int BM = MR*16, TPR = NTHR/BM, KPT = 32/TPR, NP2 = KPT/2;
    const int tid = threadIdx.x;
    const int tx = tid & 31, ty = tid >> 5;
    const int mr0 = ty*MR;
    const int j = n0 + tx;
    const int ra = tid / TPR, kq = (tid % TPR)*KPT, kq2 = kq >> 1;
    const int wrow = tid >> 2;                 // W staging: tid < 384
    const int wg = wrow >> 5, wn = wrow & 31, wk = (tid & 3)*8, wk2 = (tid & 3)*4;

    __syncthreads();
    for (int idx = tid; idx < BM*Iq; idx += NTHR){
        int r = idx/Iq, c = idx - r*Iq;
        float v;
        if (DEC && tt == 0) v = (c == Iq-1) ? 1.f : 0.f;
        else v = __ldg(&x[(m0 + r)*(Tq*Iq) + (DEC ? tt-1 : tt)*Iq + c]);
        sm->Xs[r][c] = v;
    }
    for (int idx = tid; idx < 3*32*Iq; idx += NTHR){
        int g = idx/(32*Iq); int rem = idx - g*32*Iq; int n = rem/Iq, c = rem - n*Iq;
        sm->Wis[g][n][c] = __ldg(&Wih[(g*Hq + n0 + n)*ihs + c]);
    }

    unsigned long long accr[MR], accz[MR], accn[MR];
    #pragma unroll
    for (int i = 0; i < MR; i++){ accr[i]=0ull; accz[i]=0ull; accn[i]=0ull; }

    float pa[8]; float4 pw0, pw1;
    const float* ab = hold + (m0 + ra)*Hq + kq;
    const float* wb = (tid < 384) ? (Whh + (wg*Hq + n0 + wn)*Hq + wk) : Whh;
    #pragma unroll
    for (int q = 0; q < KPT/4; q++) *(float4*)&pa[4*q] = __ldcg((const float4*)(ab + 4*q));
    pw0 = __ldg((const float4*)wb); pw1 = __ldg((const float4*)(wb + 4));

    for (int kb = 0; kb < 32; kb++){
        __syncthreads();
        #pragma unroll
        for (int q = 0; q < NP2; q++)
            sm->As2[kq2 + q][ra] = make_float2(pa[2*q], pa[2*q+1]);
        if (tid < 384){
            sm->Ws2[wg][wn][wk2+0] = make_float2(pw0.x, pw0.y);
            sm->Ws2[wg][wn][wk2+1] = make_float2(pw0.z, pw0.w);
            sm->Ws2[wg][wn][wk2+2] = make_float2(pw1.x, pw1.y);
            sm->Ws2[wg][wn][wk2+3] = make_float2(pw1.z, pw1.w);
        }
        __syncthreads();
        if (kb < 31){
            int ko = (kb+1)*32;
            #pragma unroll
            for (int q = 0; q < KPT/4; q++)
                *(float4*)&pa[4*q] = __ldcg((const float4*)(ab + ko + 4*q));
            pw0 = __ldg((const float4*)(wb + ko)); pw1 = __ldg((const float4*)(wb + ko + 4));
        }
        #pragma unroll 8
        for (int k2 = 0; k2 < 16; k2++){
            unsigned long long wr  = lds2(&sm->Ws2[0][tx][k2].x);
            unsigned long long wz  = lds2(&sm->Ws2[1][tx][k2].x);
            unsigned long long wn2 = lds2(&sm->Ws2[2][tx][k2].x);
            #pragma unroll
            for (int h = 0; h < MR/2; h++){
                ulonglong2 a = *(const ulonglong2*)&sm->As2[k2][mr0 + 2*h];
                fma2(accr[2*h],  a.x, wr); fma2(accz[2*h],  a.x, wz); fma2(accn[2*h],  a.x, wn2);
                fma2(accr[2*h+1],a.y, wr); fma2(accz[2*h+1],a.y, wz); fma2(accn[2*h+1],a.y, wn2);
            }
        }
    }

    float cr = __ldg(&bhh[j]), cz = __ldg(&bhh[Hq+j]), cn = __ldg(&bhh[2*Hq+j]);
    float br = 0, bz = 0, bn = 0;
    if (!DEC){ br = __ldg(&bih[j]); bz = __ldg(&bih[Hq+j]); bn = __ldg(&bih[2*Hq+j]); }

    #pragma unroll
    for (int r = 0; r < MR; r++){
        int row = mr0 + r, m = m0 + row;
        float l0, h0, l1, h1, l2, h2;
        up2(accr[r], l0, h0); up2(accz[r], l1, h1); up2(accn[r], l2, h2);
        float sr = l0 + h0, sz = l1 + h1, sn = l2 + h2;
        float xr = 0.f, xz = 0.f, xn = 0.f;
        #pragma unroll
        for (int c = 0; c < Iq; c++){
            float xv = sm->Xs[row][c];
            xr += xv*sm->Wis[0][tx][c];
            xz += xv*sm->Wis[1][tx][c];
            xn += xv*sm->Wis[2][tx][c];
        }
        emit<DEC>(sr + xr, sz + xz, sn, xn, m, j, br, bz, bn, cr, cz, cn, hold, hnew);
    }
}

__global__ void __launch_bounds__(NTHR, 1) vae_kernel(
    const float* __restrict__ x, const float* __restrict__ noise,
    const float* __restrict__ Wih_f, const float* __restrict__ Whh_f,
    const float* __restrict__ bih_f, const float* __restrict__ bhh_f,
    const float* __restrict__ Wih_b, const float* __restrict__ Whh_b,
    const float* __restrict__ bih_b, const float* __restrict__ bhh_b,
    const float* __restrict__ Wmu,  const float* __restrict__ bmu,
    const float* __restrict__ Wvar, const float* __restrict__ bvar,
    const float* __restrict__ Winit,const float* __restrict__ binit,
    const float* __restrict__ Wout, const float* __restrict__ bout,
    const float* __restrict__ Wcih, const float* __restrict__ Wchh,
    const float* __restrict__ bcih, const float* __restrict__ bchh,
    float* __restrict__ out)
{
    __shared__ Smem sm;
    const int blk = blockIdx.x, tid = threadIdx.x;
    const int lane = tid & 31;
    const int gwp = blk*16 + (tid >> 5);

    for (int i = blk*NTHR + tid; i < Bq*Hq; i += NBLK*NTHR){
        g_hf[0][i] = 0.f; g_hb[0][i] = 0.f;
    }
    gbar();

    const int edir = blk >> 6, erem = blk & 63;
    const int em0 = (erem >> 5)*128, en0 = (erem & 31)*32;
    for (int t = 0; t < Tq; t++){
        int par = t & 1;
        if (edir == 0)
            gru_tile<8,0>(&sm, x, t, Wih_f, Iq, Whh_f, bih_f, bhh_f,
                          g_hf[par], g_hf[par^1], em0, en0);
        else
            gru_tile<8,0>(&sm, x, Tq-1-t, Wih_b, Iq, Whh_b, bih_b, bhh_b,
                          g_hb[par], g_hb[par^1], em0, en0);
        gbar();
    }

    for (int it = gwp; it < Bq*Zq; it += NWARP){
        int m = it >> 7, zi = it & 127;
        const float* hf = &g_hf[0][m*Hq];
        const float* hb = &g_hb[0][m*Hq];
        const float* wm = &Wmu[zi*2*Hq];
        const float* wv = &Wvar[zi*2*Hq];
        float am = 0.f, av = 0.f;
        for (int k = lane; k < Hq; k += 32){
            float h1 = __ldcg(&hf[k]); am += h1*__ldg(&wm[k]);    av += h1*__ldg(&wv[k]);
            float h2 = __ldcg(&hb[k]); am += h2*__ldg(&wm[Hq+k]); av += h2*__ldg(&wv[Hq+k]);
        }
        am = wred(am); av = wred(av);
        if (lane == 0){
            float mean = am + __ldg(&bmu[zi]);
            float sd = expf(0.5f*(av + __ldg(&bvar[zi])));
            out[OFF_MEAN + m*Zq + zi] = mean;
            out[OFF_STD  + m*Zq + zi] = sd;
            g_z[m*Zq + zi] = mean + sd*__ldg(&noise[m*Zq + zi]);
        }
    }
    gbar();

    for (int it = gwp; it < Bq*G3; it += NWARP){
        int m = it / G3, gc = it - m*G3;
        const float* zr = &g_z[m*Zq];
        const float* wr = &Wcih[gc*(Iq + Zq) + Iq];
        float acc = 0.f;
        for (int k = lane; k < Zq; k += 32) acc += __ldcg(&zr[k])*__ldg(&wr[k]);
        acc = wred(acc);
        if (lane == 0) g_giz[m*G3 + gc] = acc + __ldg(&bcih[gc]);
    }
    for (int it = gwp; it < Bq*Hq; it += NWARP){
        int m = it >> 10, jj = it & 1023;
        const float* zr = &g_z[m*Zq];
        const float* wr = &Winit[jj*Zq];
        float acc = 0.f;
        for (int k = lane; k < Zq; k += 32) acc += __ldcg(&zr[k])*__ldg(&wr[k]);
        acc = wred(acc);
        if (lane == 0) g_hd[0][m*Hq + jj] = tanhf(acc + __ldg(&binit[jj]));
    }
    gbar();

    const int dm0 = (blk >> 5)*64, dn0 = (blk & 31)*32;
    for (int t = 0; t < Tq; t++){
        int par = t & 1;
        if (t > 0){
            const float* hbuf = g_hd[par];
            for (int it = gwp; it < Bq*Iq; it += NWARP){
                int m = it / Iq, i = it - m*Iq;
                const float* h = &hbuf[m*Hq];
                const float* w = &Wout[i*Hq];
                float acc = 0.f;
                for (int k = lane; k < Hq; k += 32) acc += __ldcg(&h[k])*__ldg(&w[k]);
                acc = wred(acc);
                if (lane == 0)
                    out[m*(Tq*Iq) + (t-1)*Iq + i] = sgm(acc + __ldg(&bout[i]));
            }
        }
        gru_tile<4,1>(&sm, x, t, Wcih, Iq + Zq, Wchh, bcih, bchh,
                      g_hd[par], g_hd[par^1], dm0, dn0);
        gbar();
    }

    {
        const float* hbuf = g_hd[0];
        for (int it = gwp; it < Bq*Iq; it += NWARP){
            int m = it / Iq, i = it - m*Iq;
            const float* h = &hbuf[m*Hq];
            const float* w = &Wout[i*Hq];
            float acc = 0.f;
            for (int k = lane; k < Hq; k += 32) acc += __ldcg(&h[k])*__ldg(&w[k]);
            acc = wred(acc);
            if (lane == 0)
                out[m*(Tq*Iq) + (Tq-1)*Iq + i] = sgm(acc + __ldg(&bout[i]));
        }
    }
}

extern "C" void kernel_launch(void* const* d_in, const int* in_sizes, int n_in,
                              void* d_out, int out_size)
{
    vae_kernel<<<NBLK, NTHR>>>(
        (const float*)d_in[0],  (const float*)d_in[1],
        (const float*)d_in[2],  (const float*)d_in[3],
        (const float*)d_in[4],  (const float*)d_in[5],
        (const float*)d_in[6],  (const float*)d_in[7],
        (const float*)d_in[8],  (const float*)d_in[9],
        (const float*)d_in[10], (const float*)d_in[11],
        (const float*)d_in[12], (const float*)d_in[13],
        (const float*)d_in[14], (const float*)d_in[15],
        (const float*)d_in[16], (const float*)d_in[17],
        (const float*)d_in[18], (const float*)d_in[19],
        (const float*)d_in[20], (const float*)d_in[21],
        (float*)d_out);
}

// round 13
// speedup vs baseline: 1.3600x; 1.0355x over previous
#include <cuda_runtime.h>
#include <math.h>

#define Bq 256
#define Tq 512
#define Iq 12
#define Hq 1024
#define Zq 128
#define G3 3072
#define NBLK 128
#define NTHR 512
#define NWARP 2048
#define OFF_MEAN (Bq*Tq*Iq)
#define OFF_STD  (OFF_MEAN + Bq*Zq)

// dynamic smem layout (bytes)
#define A0o 0
#define A1o 16640
#define W0o 33280
#define W1o 46336
#define XSo 59392
#define WISo 65536
#define SMTOT 70144

__device__ float g_hf[2][Bq*Hq];
__device__ float g_hb[2][Bq*Hq];
__device__ float g_hd[2][Bq*Hq];
__device__ float g_z[Bq*Zq];
__device__ float g_giz[Bq*G3];
__device__ unsigned g_cnt = 0;
__device__ unsigned g_gen = 0;

__device__ __forceinline__ void up2(unsigned long long v, float& lo, float& hi){
    asm("mov.b64 {%0,%1}, %2;" : "=f"(lo), "=f"(hi) : "l"(v));
}
__device__ __forceinline__ void fma2(unsigned long long& a, unsigned long long x, unsigned long long y){
    asm("fma.rn.f32x2 %0, %1, %2, %0;" : "+l"(a) : "l"(x), "l"(y));
}
__device__ __forceinline__ unsigned long long lds2(const float2* p){
    return *reinterpret_cast<const unsigned long long*>(p);
}
#define CPA8(dst, src) asm volatile("cp.async.ca.shared.global [%0], [%1], 8;"::"r"(dst),"l"(src):"memory")
#define CPC()  asm volatile("cp.async.commit_group;":::"memory")
#define CPW0() asm volatile("cp.async.wait_group 0;":::"memory")

__device__ __forceinline__ float sgm(float v){ return 1.f/(1.f + expf(-v)); }
__device__ __forceinline__ float wred(float v){
    #pragma unroll
    for (int o = 16; o > 0; o >>= 1) v += __shfl_down_sync(0xffffffffu, v, o);
    return v;
}
__device__ __forceinline__ void gbar(){
    __syncthreads();
    if (threadIdx.x == 0){
        unsigned my = *(volatile unsigned*)&g_gen;
        __threadfence();
        if (atomicAdd(&g_cnt, 1u) == NBLK - 1u){
            atomicExch(&g_cnt, 0u);
            __threadfence();
            atomicAdd(&g_gen, 1u);
        } else {
            while (*(volatile unsigned*)&g_gen == my) __nanosleep(32);
            __threadfence();
        }
    }
    __syncthreads();
}

template<int DEC>
__device__ __forceinline__ void emit(float sr, float sz, float sn, float gx,
    int m, int j, float br, float bz, float bn, float cr, float cz, float cn,
    const float* __restrict__ hold, float* __restrict__ hnew)
{
    float gr = br, gz = bz, gn = bn;
    if (DEC){
        gr = __ldcg(&g_giz[m*G3 + j]);
        gz = __ldcg(&g_giz[m*G3 + Hq + j]);
        gn = __ldcg(&g_giz[m*G3 + 2*Hq + j]);
    }
    float rr = sgm(sr + gr + cr);
    float zz = sgm(sz + gz + cz);
    float nn = tanhf(gx + gn + rr*(sn + cn));
    float ho = __ldcg(&hold[m*Hq + j]);
    hnew[m*Hq + j] = (1.f - zz)*nn + zz*ho;
}

// MR rows/thread: 8 -> BM=128 (encoder), 4 -> BM=64 (decoder). f32x2 over k-pairs.
template<int MR, int DEC>
__device__ __forceinline__ void gru_tile(char* smc, unsigned smu,
    const float* __restrict__ x, int tt,
    const float* __restrict__ Wih, int ihs,
    const float* __restrict__ Whh,
    const float* __restrict__ bih, const float* __restrict__ bhh,
    const float* __restrict__ hold, float* __restrict__ hnew,
    int m0, int n0)
{
    const int BM = MR*16, TPR = NTHR/BM, KPT = 32/TPR, NP2 = KPT/2;
    const int tid = threadIdx.x;
    const int tx = tid & 31, ty = tid >> 5;
    const int mr0 = ty*MR;
    const int j = n0 + tx;
    const int ra = tid / TPR, kq = (tid % TPR)*KPT, kq2 = kq >> 1;

    float* Xs = (float*)(smc + XSo);
    float* Wis = (float*)(smc + WISo);

    // ---- W(0) via cp.async, A(0) via LDG prefetch ----
    float pa[KPT];
    const float* ab = hold + (m0 + ra)*Hq + kq;
    #pragma unroll
    for (int q = 0; q < KPT/4; q++) *(float4*)&pa[4*q] = __ldcg((const float4*)(ab + 4*q));
    #pragma unroll
    for (int q = 0; q < 3; q++){
        int idx = tid + 512*q;
        int row = idx >> 4, ch = idx & 15;
        const float* src = Whh + ((row>>5)*Hq + n0 + (row&31))*Hq + ch*2;
        CPA8(smu + W0o + row*136 + ch*8, src);
    }
    CPC();

    // ---- Xs / Wis staging (consumed in epilogue; mainloop syncs cover it) ----
    for (int idx = tid; idx < BM*Iq; idx += NTHR){
        int r = idx/Iq, c = idx - r*Iq;
        float v;
        if (DEC && tt == 0) v = (c == Iq-1) ? 1.f : 0.f;
        else v = __ldg(&x[(m0 + r)*(Tq*Iq) + (DEC ? tt-1 : tt)*Iq + c]);
        Xs[r*Iq + c] = v;
    }
    for (int idx = tid; idx < 3*32*Iq; idx += NTHR){
        int g = idx/(32*Iq); int rem = idx - g*32*Iq; int n = rem/Iq, c = rem - n*Iq;
        Wis[(g*32 + n)*Iq + c] = __ldg(&Wih[(g*Hq + n0 + n)*ihs + c]);
    }

    unsigned long long accr[MR], accz[MR], accn[MR];
    #pragma unroll
    for (int i = 0; i < MR; i++){ accr[i]=0ull; accz[i]=0ull; accn[i]=0ull; }

    #pragma unroll 1
    for (int kb = 0; kb < 32; kb++){
        const int b = kb & 1;
        float2* Af2 = (float2*)(smc + (b ? A1o : A0o));
        const float2* Wf2 = (const float2*)(smc + (b ? W1o : W0o));
        // store A(kb), prefetch A(kb+1)
        #pragma unroll
        for (int q = 0; q < NP2; q++)
            Af2[(kq2 + q)*130 + ra] = make_float2(pa[2*q], pa[2*q+1]);
        if (kb < 31){
            int ko = (kb+1)*32;
            #pragma unroll
            for (int q = 0; q < KPT/4; q++)
                *(float4*)&pa[4*q] = __ldcg((const float4*)(ab + ko + 4*q));
        }
        CPW0();                // W(kb) landed
        __syncthreads();       // buf[b] fully staged; all warps done with buf[b^1]
        if (kb < 31){          // W(kb+1) -> other buffer, overlapped with compute
            int ko = (kb+1)*32;
            #pragma unroll
            for (int q = 0; q < 3; q++){
                int idx = tid + 512*q;
                int row = idx >> 4, ch = idx & 15;
                const float* src = Whh + ((row>>5)*Hq + n0 + (row&31))*Hq + ko + ch*2;
                CPA8(smu + (b ? W0o : W1o) + row*136 + ch*8, src);
            }
            CPC();
        }
        #pragma unroll 8
        for (int k2 = 0; k2 < 16; k2++){
            unsigned long long wr  = lds2(&Wf2[(tx)*17 + k2]);
            unsigned long long wz  = lds2(&Wf2[(32 + tx)*17 + k2]);
            unsigned long long wn2 = lds2(&Wf2[(64 + tx)*17 + k2]);
            #pragma unroll
            for (int h = 0; h < MR/2; h++){
                ulonglong2 a = *(const ulonglong2*)&Af2[k2*130 + mr0 + 2*h];
                fma2(accr[2*h],  a.x, wr); fma2(accz[2*h],  a.x, wz); fma2(accn[2*h],  a.x, wn2);
                fma2(accr[2*h+1],a.y, wr); fma2(accz[2*h+1],a.y, wz); fma2(accn[2*h+1],a.y, wn2);
            }
        }
    }

    float cr = __ldg(&bhh[j]), cz = __ldg(&bhh[Hq+j]), cn = __ldg(&bhh[2*Hq+j]);
    float br = 0, bz = 0, bn = 0;
    if (!DEC){ br = __ldg(&bih[j]); bz = __ldg(&bih[Hq+j]); bn = __ldg(&bih[2*Hq+j]); }

    #pragma unroll
    for (int r = 0; r < MR; r++){
        int row = mr0 + r, m = m0 + row;
        float l0, h0, l1, h1, l2, h2;
        up2(accr[r], l0, h0); up2(accz[r], l1, h1); up2(accn[r], l2, h2);
        float sr = l0 + h0, sz = l1 + h1, sn = l2 + h2;
        float xr = 0.f, xz = 0.f, xn = 0.f;
        #pragma unroll
        for (int c = 0; c < Iq; c++){
            float xv = Xs[row*Iq + c];
            xr += xv*Wis[(tx)*Iq + c];
            xz += xv*Wis[(32 + tx)*Iq + c];
            xn += xv*Wis[(64 + tx)*Iq + c];
        }
        emit<DEC>(sr + xr, sz + xz, sn, xn, m, j, br, bz, bn, cr, cz, cn, hold, hnew);
    }
}

__global__ void __launch_bounds__(NTHR, 1) vae_kernel(
    const float* __restrict__ x, const float* __restrict__ noise,
    const float* __restrict__ Wih_f, const float* __restrict__ Whh_f,
    const float* __restrict__ bih_f, const float* __restrict__ bhh_f,
    const float* __restrict__ Wih_b, const float* __restrict__ Whh_b,
    const float* __restrict__ bih_b, const float* __restrict__ bhh_b,
    const float* __restrict__ Wmu,  const float* __restrict__ bmu,
    const float* __restrict__ Wvar, const float* __restrict__ bvar,
    const float* __restrict__ Winit,const float* __restrict__ binit,
    const float* __restrict__ Wout, const float* __restrict__ bout,
    const float* __restrict__ Wcih, const float* __restrict__ Wchh,
    const float* __restrict__ bcih, const float* __restrict__ bchh,
    float* __restrict__ out)
{
    extern __shared__ char smc[];
    unsigned smu;
    { unsigned long long t; asm("cvta.to.shared.u64 %0, %1;":"=l"(t):"l"(smc)); smu = (unsigned)t; }
    const int blk = blockIdx.x, tid = threadIdx.x;
    const int lane = tid & 31;
    const int gwp = blk*16 + (tid >> 5);

    for (int i = blk*NTHR + tid; i < Bq*Hq; i += NBLK*NTHR){
        g_hf[0][i] = 0.f; g_hb[0][i] = 0.f;
    }
    gbar();

    const int edir = blk >> 6, erem = blk & 63;
    const int em0 = (erem >> 5)*128, en0 = (erem & 31)*32;
    for (int t = 0; t < Tq; t++){
        int par = t & 1;
        if (edir == 0)
            gru_tile<8,0>(smc, smu, x, t, Wih_f, Iq, Whh_f, bih_f, bhh_f,
                          g_hf[par], g_hf[par^1], em0, en0);
        else
            gru_tile<8,0>(smc, smu, x, Tq-1-t, Wih_b, Iq, Whh_b, bih_b, bhh_b,
                          g_hb[par], g_hb[par^1], em0, en0);
        gbar();
    }

    for (int it = gwp; it < Bq*Zq; it += NWARP){
        int m = it >> 7, zi = it & 127;
        const float* hf = &g_hf[0][m*Hq];
        const float* hb = &g_hb[0][m*Hq];
        const float* wm = &Wmu[zi*2*Hq];
        const float* wv = &Wvar[zi*2*Hq];
        float am = 0.f, av = 0.f;
        for (int k = lane; k < Hq; k += 32){
            float h1 = __ldcg(&hf[k]); am += h1*__ldg(&wm[k]);    av += h1*__ldg(&wv[k]);
            float h2 = __ldcg(&hb[k]); am += h2*__ldg(&wm[Hq+k]); av += h2*__ldg(&wv[Hq+k]);
        }
        am = wred(am); av = wred(av);
        if (lane == 0){
            float mean = am + __ldg(&bmu[zi]);
            float sd = expf(0.5f*(av + __ldg(&bvar[zi])));
            out[OFF_MEAN + m*Zq + zi] = mean;
            out[OFF_STD  + m*Zq + zi] = sd;
            g_z[m*Zq + zi] = mean + sd*__ldg(&noise[m*Zq + zi]);
        }
    }
    gbar();

    for (int it = gwp; it < Bq*G3; it += NWARP){
        int m = it / G3, gc = it - m*G3;
        const float* zr = &g_z[m*Zq];
        const float* wr = &Wcih[gc*(Iq + Zq) + Iq];
        float acc = 0.f;
        for (int k = lane; k < Zq; k += 32) acc += __ldcg(&zr[k])*__ldg(&wr[k]);
        acc = wred(acc);
        if (lane == 0) g_giz[m*G3 + gc] = acc + __ldg(&bcih[gc]);
    }
    for (int it = gwp; it < Bq*Hq; it += NWARP){
        int m = it >> 10, jj = it & 1023;
        const float* zr = &g_z[m*Zq];
        const float* wr = &Winit[jj*Zq];
        float acc = 0.f;
        for (int k = lane; k < Zq; k += 32) acc += __ldcg(&zr[k])*__ldg(&wr[k]);
        acc = wred(acc);
        if (lane == 0) g_hd[0][m*Hq + jj] = tanhf(acc + __ldg(&binit[jj]));
    }
    gbar();

    const int dm0 = (blk >> 5)*64, dn0 = (blk & 31)*32;
    for (int t = 0; t < Tq; t++){
        int par = t & 1;
        if (t > 0){
            const float* hbuf = g_hd[par];
            for (int it = gwp; it < Bq*Iq; it += NWARP){
                int m = it / Iq, i = it - m*Iq;
                const float* h = &hbuf[m*Hq];
                const float* w = &Wout[i*Hq];
                float acc = 0.f;
                for (int k = lane; k < Hq; k += 32) acc += __ldcg(&h[k])*__ldg(&w[k]);
                acc = wred(acc);
                if (lane == 0)
                    out[m*(Tq*Iq) + (t-1)*Iq + i] = sgm(acc + __ldg(&bout[i]));
            }
        }
        gru_tile<4,1>(smc, smu, x, t, Wcih, Iq + Zq, Wchh, bcih, bchh,
                      g_hd[par], g_hd[par^1], dm0, dn0);
        gbar();
    }

    {
        const float* hbuf = g_hd[0];
        for (int it = gwp; it < Bq*Iq; it += NWARP){
            int m = it / Iq, i = it - m*Iq;
            const float* h = &hbuf[m*Hq];
            const float* w = &Wout[i*Hq];
            float acc = 0.f;
            for (int k = lane; k < Hq; k += 32) acc += __ldcg(&h[k])*__ldg(&w[k]);
            acc = wred(acc);
            if (lane == 0)
                out[m*(Tq*Iq) + (Tq-1)*Iq + i] = sgm(acc + __ldg(&bout[i]));
        }
    }
}

extern "C" void kernel_launch(void* const* d_in, const int* in_sizes, int n_in,
                              void* d_out, int out_size)
{
    cudaFuncSetAttribute(vae_kernel, cudaFuncAttributeMaxDynamicSharedMemorySize, SMTOT);
    vae_kernel<<<NBLK, NTHR, SMTOT>>>(
        (const float*)d_in[0],  (const float*)d_in[1],
        (const float*)d_in[2],  (const float*)d_in[3],
        (const float*)d_in[4],  (const float*)d_in[5],
        (const float*)d_in[6],  (const float*)d_in[7],
        (const float*)d_in[8],  (const float*)d_in[9],
        (const float*)d_in[10], (const float*)d_in[11],
        (const float*)d_in[12], (const float*)d_in[13],
        (const float*)d_in[14], (const float*)d_in[15],
        (const float*)d_in[16], (const float*)d_in[17],
        (const float*)d_in[18], (const float*)d_in[19],
        (const float*)d_in[20], (const float*)d_in[21],
        (float*)d_out);
}

// round 14
// speedup vs baseline: 1.3674x; 1.0054x over previous
#include <cuda_runtime.h>
#include <math.h>

#define Bq 256
#define Tq 512
#define Iq 12
#define Hq 1024
#define Zq 128
#define G3 3072
#define NBLK 128
#define NTHR 512
#define NWARP 2048
#define OFF_MEAN (Bq*Tq*Iq)
#define OFF_STD  (OFF_MEAN + Bq*Zq)

// dynamic smem layout (bytes)
#define A0o 0
#define A1o 16640
#define W0o 33280
#define W1o 46336
#define XSo 59392
#define WISo 65536
#define SMTOT 70144

__device__ float g_hf[2][Bq*Hq];
__device__ float g_hb[2][Bq*Hq];
__device__ float g_hd[2][Bq*Hq];
__device__ float g_z[Bq*Zq];
__device__ float g_giz[Bq*G3];
__device__ unsigned g_cnt = 0;
__device__ unsigned g_gen = 0;

__device__ __forceinline__ void up2(unsigned long long v, float& lo, float& hi){
    asm("mov.b64 {%0,%1}, %2;" : "=f"(lo), "=f"(hi) : "l"(v));
}
__device__ __forceinline__ void fma2(unsigned long long& a, unsigned long long x, unsigned long long y){
    asm("fma.rn.f32x2 %0, %1, %2, %0;" : "+l"(a) : "l"(x), "l"(y));
}
__device__ __forceinline__ unsigned long long lds2(const float2* p){
    return *reinterpret_cast<const unsigned long long*>(p);
}
#define CPA8(dst, src) asm volatile("cp.async.ca.shared.global [%0], [%1], 8;"::"r"(dst),"l"(src):"memory")
#define CPC()  asm volatile("cp.async.commit_group;":::"memory")
#define CPW0() asm volatile("cp.async.wait_group 0;":::"memory")

__device__ __forceinline__ float sgm(float v){ return 1.f/(1.f + expf(-v)); }
__device__ __forceinline__ float wred(float v){
    #pragma unroll
    for (int o = 16; o > 0; o >>= 1) v += __shfl_down_sync(0xffffffffu, v, o);
    return v;
}
__device__ __forceinline__ void gbar(){
    __syncthreads();
    if (threadIdx.x == 0){
        unsigned my = *(volatile unsigned*)&g_gen;
        __threadfence();
        if (atomicAdd(&g_cnt, 1u) == NBLK - 1u){
            atomicExch(&g_cnt, 0u);
            __threadfence();
            atomicAdd(&g_gen, 1u);
        } else {
            while (*(volatile unsigned*)&g_gen == my) __nanosleep(32);
            __threadfence();
        }
    }
    __syncthreads();
}

template<int DEC>
__device__ __forceinline__ void emit(float sr, float sz, float sn, float gx,
    int m, int j, float br, float bz, float bn, float cr, float cz, float cn,
    const float* __restrict__ hold, float* __restrict__ hnew)
{
    float gr = br, gz = bz, gn = bn;
    if (DEC){
        gr = __ldcg(&g_giz[m*G3 + j]);
        gz = __ldcg(&g_giz[m*G3 + Hq + j]);
        gn = __ldcg(&g_giz[m*G3 + 2*Hq + j]);
    }
    float rr = sgm(sr + gr + cr);
    float zz = sgm(sz + gz + cz);
    float nn = tanhf(gx + gn + rr*(sn + cn));
    float ho = __ldcg(&hold[m*Hq + j]);
    hnew[m*Hq + j] = (1.f - zz)*nn + zz*ho;
}

// MR rows/thread: 8 -> BM=128 (encoder), 4 -> BM=64 (decoder). f32x2 over k-pairs.
template<int MR, int DEC>
__device__ __forceinline__ void gru_tile(char* smc, unsigned smu,
    const float* __restrict__ x, int tt,
    const float* __restrict__ Wih, int ihs,
    const float* __restrict__ Whh,
    const float* __restrict__ bih, const float* __restrict__ bhh,
    const float* __restrict__ hold, float* __restrict__ hnew,
    int m0, int n0)
{
    const int BM = MR*16, TPR = NTHR/BM, KPT = 32/TPR, NP2 = KPT/2;
    const int tid = threadIdx.x;
    const int tx = tid & 31, ty = tid >> 5;
    const int mr0 = ty*MR;
    const int j = n0 + tx;
    const int ra = tid / TPR, kq = (tid % TPR)*KPT, kq2 = kq >> 1;

    float* Xs = (float*)(smc + XSo);
    float* Wis = (float*)(smc + WISo);

    // ---- W(0) via cp.async, A(0) via LDG prefetch ----
    float pa[KPT];
    const float* ab = hold + (m0 + ra)*Hq + kq;
    #pragma unroll
    for (int q = 0; q < KPT/4; q++) *(float4*)&pa[4*q] = __ldcg((const float4*)(ab + 4*q));
    #pragma unroll
    for (int q = 0; q < 3; q++){
        int idx = tid + 512*q;
        int row = idx >> 4, ch = idx & 15;
        const float* src = Whh + ((row>>5)*Hq + n0 + (row&31))*Hq + ch*2;
        CPA8(smu + W0o + row*136 + ch*8, src);
    }
    CPC();

    // ---- Xs / Wis staging (consumed in epilogue; mainloop syncs cover it) ----
    for (int idx = tid; idx < BM*Iq; idx += NTHR){
        int r = idx/Iq, c = idx - r*Iq;
        float v;
        if (DEC && tt == 0) v = (c == Iq-1) ? 1.f : 0.f;
        else v = __ldg(&x[(m0 + r)*(Tq*Iq) + (DEC ? tt-1 : tt)*Iq + c]);
        Xs[r*Iq + c] = v;
    }
    for (int idx = tid; idx < 3*32*Iq; idx += NTHR){
        int g = idx/(32*Iq); int rem = idx - g*32*Iq; int n = rem/Iq, c = rem - n*Iq;
        Wis[(g*32 + n)*Iq + c] = __ldg(&Wih[(g*Hq + n0 + n)*ihs + c]);
    }

    unsigned long long accr[MR], accz[MR], accn[MR];
    #pragma unroll
    for (int i = 0; i < MR; i++){ accr[i]=0ull; accz[i]=0ull; accn[i]=0ull; }

    #pragma unroll 1
    for (int kb = 0; kb < 32; kb++){
        const int b = kb & 1;
        float2* Af2 = (float2*)(smc + (b ? A1o : A0o));
        const float2* Wf2 = (const float2*)(smc + (b ? W1o : W0o));
        // store A(kb), prefetch A(kb+1)
        #pragma unroll
        for (int q = 0; q < NP2; q++)
            Af2[(kq2 + q)*130 + ra] = make_float2(pa[2*q], pa[2*q+1]);
        if (kb < 31){
            int ko = (kb+1)*32;
            #pragma unroll
            for (int q = 0; q < KPT/4; q++)
                *(float4*)&pa[4*q] = __ldcg((const float4*)(ab + ko + 4*q));
        }
        CPW0();                // W(kb) landed
        __syncthreads();       // buf[b] fully staged; all warps done with buf[b^1]
        if (kb < 31){          // W(kb+1) -> other buffer, overlapped with compute
            int ko = (kb+1)*32;
            #pragma unroll
            for (int q = 0; q < 3; q++){
                int idx = tid + 512*q;
                int row = idx >> 4, ch = idx & 15;
                const float* src = Whh + ((row>>5)*Hq + n0 + (row&31))*Hq + ko + ch*2;
                CPA8(smu + (b ? W0o : W1o) + row*136 + ch*8, src);
            }
            CPC();
        }
        #pragma unroll 8
        for (int k2 = 0; k2 < 16; k2++){
            unsigned long long wr  = lds2(&Wf2[(tx)*17 + k2]);
            unsigned long long wz  = lds2(&Wf2[(32 + tx)*17 + k2]);
            unsigned long long wn2 = lds2(&Wf2[(64 + tx)*17 + k2]);
            #pragma unroll
            for (int h = 0; h < MR/2; h++){
                ulonglong2 a = *(const ulonglong2*)&Af2[k2*130 + mr0 + 2*h];
                fma2(accr[2*h],  a.x, wr); fma2(accz[2*h],  a.x, wz); fma2(accn[2*h],  a.x, wn2);
                fma2(accr[2*h+1],a.y, wr); fma2(accz[2*h+1],a.y, wz); fma2(accn[2*h+1],a.y, wn2);
            }
        }
    }

    float cr = __ldg(&bhh[j]), cz = __ldg(&bhh[Hq+j]), cn = __ldg(&bhh[2*Hq+j]);
    float br = 0, bz = 0, bn = 0;
    if (!DEC){ br = __ldg(&bih[j]); bz = __ldg(&bih[Hq+j]); bn = __ldg(&bih[2*Hq+j]); }

    #pragma unroll
    for (int r = 0; r < MR; r++){
        int row = mr0 + r, m = m0 + row;
        float l0, h0, l1, h1, l2, h2;
        up2(accr[r], l0, h0); up2(accz[r], l1, h1); up2(accn[r], l2, h2);
        float sr = l0 + h0, sz = l1 + h1, sn = l2 + h2;
        float xr = 0.f, xz = 0.f, xn = 0.f;
        #pragma unroll
        for (int c = 0; c < Iq; c++){
            float xv = Xs[row*Iq + c];
            xr += xv*Wis[(tx)*Iq + c];
            xz += xv*Wis[(32 + tx)*Iq + c];
            xn += xv*Wis[(64 + tx)*Iq + c];
        }
        emit<DEC>(sr + xr, sz + xz, sn, xn, m, j, br, bz, bn, cr, cz, cn, hold, hnew);
    }
}

__global__ void __launch_bounds__(NTHR, 1) vae_kernel(
    const float* __restrict__ x, const float* __restrict__ noise,
    const float* __restrict__ Wih_f, const float* __restrict__ Whh_f,
    const float* __restrict__ bih_f, const float* __restrict__ bhh_f,
    const float* __restrict__ Wih_b, const float* __restrict__ Whh_b,
    const float* __restrict__ bih_b, const float* __restrict__ bhh_b,
    const float* __restrict__ Wmu,  const float* __restrict__ bmu,
    const float* __restrict__ Wvar, const float* __restrict__ bvar,
    const float* __restrict__ Winit,const float* __restrict__ binit,
    const float* __restrict__ Wout, const float* __restrict__ bout,
    const float* __restrict__ Wcih, const float* __restrict__ Wchh,
    const float* __restrict__ bcih, const float* __restrict__ bchh,
    float* __restrict__ out)
{
    extern __shared__ char smc[];
    unsigned smu;
    { unsigned long long t; asm("cvta.to.shared.u64 %0, %1;":"=l"(t):"l"(smc)); smu = (unsigned)t; }
    const int blk = blockIdx.x, tid = threadIdx.x;
    const int lane = tid & 31;
    const int gwp = blk*16 + (tid >> 5);

    for (int i = blk*NTHR + tid; i < Bq*Hq; i += NBLK*NTHR){
        g_hf[0][i] = 0.f; g_hb[0][i] = 0.f;
    }
    gbar();

    const int edir = blk >> 6, erem = blk & 63;
    const int em0 = (erem >> 5)*128, en0 = (erem & 31)*32;
    for (int t = 0; t < Tq; t++){
        int par = t & 1;
        if (edir == 0)
            gru_tile<8,0>(smc, smu, x, t, Wih_f, Iq, Whh_f, bih_f, bhh_f,
                          g_hf[par], g_hf[par^1], em0, en0);
        else
            gru_tile<8,0>(smc, smu, x, Tq-1-t, Wih_b, Iq, Whh_b, bih_b, bhh_b,
                          g_hb[par], g_hb[par^1], em0, en0);
        gbar();
    }

    for (int it = gwp; it < Bq*Zq; it += NWARP){
        int m = it >> 7, zi = it & 127;
        const float* hf = &g_hf[0][m*Hq];
        const float* hb = &g_hb[0][m*Hq];
        const float* wm = &Wmu[zi*2*Hq];
        const float* wv = &Wvar[zi*2*Hq];
        float am = 0.f, av = 0.f;
        for (int k = lane; k < Hq; k += 32){
            float h1 = __ldcg(&hf[k]); am += h1*__ldg(&wm[k]);    av += h1*__ldg(&wv[k]);
            float h2 = __ldcg(&hb[k]); am += h2*__ldg(&wm[Hq+k]); av += h2*__ldg(&wv[Hq+k]);
        }
        am = wred(am); av = wred(av);
        if (lane == 0){
            float mean = am + __ldg(&bmu[zi]);
            float sd = expf(0.5f*(av + __ldg(&bvar[zi])));
            out[OFF_MEAN + m*Zq + zi] = mean;
            out[OFF_STD  + m*Zq + zi] = sd;
            g_z[m*Zq + zi] = mean + sd*__ldg(&noise[m*Zq + zi]);
        }
    }
    gbar();

    for (int it = gwp; it < Bq*G3; it += NWARP){
        int m = it / G3, gc = it - m*G3;
        const float* zr = &g_z[m*Zq];
        const float* wr = &Wcih[gc*(Iq + Zq) + Iq];
        float acc = 0.f;
        for (int k = lane; k < Zq; k += 32) acc += __ldcg(&zr[k])*__ldg(&wr[k]);
        acc = wred(acc);
        if (lane == 0) g_giz[m*G3 + gc] = acc + __ldg(&bcih[gc]);
    }
    for (int it = gwp; it < Bq*Hq; it += NWARP){
        int m = it >> 10, jj = it & 1023;
        const float* zr = &g_z[m*Zq];
        const float* wr = &Winit[jj*Zq];
        float acc = 0.f;
        for (int k = lane; k < Zq; k += 32) acc += __ldcg(&zr[k])*__ldg(&wr[k]);
        acc = wred(acc);
        if (lane == 0) g_hd[0][m*Hq + jj] = tanhf(acc + __ldg(&binit[jj]));
    }
    gbar();

    const int dm0 = (blk >> 5)*64, dn0 = (blk & 31)*32;
    for (int t = 0; t < Tq; t++){
        int par = t & 1;
        if (t > 0){
            const float* hbuf = g_hd[par];
            for (int it = gwp; it < Bq*Iq; it += NWARP){
                int m = it / Iq, i = it - m*Iq;
                const float* h = &hbuf[m*Hq];
                const float* w = &Wout[i*Hq];
                float acc = 0.f;
                for (int k = lane; k < Hq; k += 32) acc += __ldcg(&h[k])*__ldg(&w[k]);
                acc = wred(acc);
                if (lane == 0)
                    out[m*(Tq*Iq) + (t-1)*Iq + i] = sgm(acc + __ldg(&bout[i]));
            }
        }
        gru_tile<4,1>(smc, smu, x, t, Wcih, Iq + Zq, Wchh, bcih, bchh,
                      g_hd[par], g_hd[par^1], dm0, dn0);
        gbar();
    }

    {
        const float* hbuf = g_hd[0];
        for (int it = gwp; it < Bq*Iq; it += NWARP){
            int m = it / Iq, i = it - m*Iq;
            const float* h = &hbuf[m*Hq];
            const float* w = &Wout[i*Hq];
            float acc = 0.f;
            for (int k = lane; k < Hq; k += 32) acc += __ldcg(&h[k])*__ldg(&w[k]);
            acc = wred(acc);
            if (lane == 0)
                out[m*(Tq*Iq) + (Tq-1)*Iq + i] = sgm(acc + __ldg(&bout[i]));
        }
    }
}

extern "C" void kernel_launch(void* const* d_in, const int* in_sizes, int n_in,
                              void* d_out, int out_size)
{
    cudaFuncSetAttribute(vae_kernel, cudaFuncAttributeMaxDynamicSharedMemorySize, SMTOT);
    vae_kernel<<<NBLK, NTHR, SMTOT>>>(
        (const float*)d_in[0],  (const float*)d_in[1],
        (const float*)d_in[2],  (const float*)d_in[3],
        (const float*)d_in[4],  (const float*)d_in[5],
        (const float*)d_in[6],  (const float*)d_in[7],
        (const float*)d_in[8],  (const float*)d_in[9],
        (const float*)d_in[10], (const float*)d_in[11],
        (const float*)d_in[12], (const float*)d_in[13],
        (const float*)d_in[14], (const float*)d_in[15],
        (const float*)d_in[16], (const float*)d_in[17],
        (const float*)d_in[18], (const float*)d_in[19],
        (const float*)d_in[20], (const float*)d_in[21],
        (float*)d_out);
}